// round 2
// baseline (speedup 1.0000x reference)
#include <cuda_runtime.h>
#include <math.h>

#define B      8
#define C      256
#define NPTS   16384
#define K      128
#define CTILE  32
#define CHUNK  256
#define NSPLIT 8
#define NPB    (NPTS / NSPLIT)   // 2048 points per block
#define BKC    (B * K * C)       // 262144

#define NEG_SENT (-3.402823e38f) // -FLT_MAX sentinel (no inf -> fast-math safe)
#define EMPTY_TH (-3.3e38f)      // anything <= this means "empty segment"

// Per-split partial maxima: [NSPLIT][B][K][C] = 8 MiB.
// Every slot written unconditionally each launch -> no init kernel needed,
// deterministic under graph replay.
__device__ float g_scratch[NSPLIT * B * K * C];

__global__ __launch_bounds__(256)
void seg_main(const float* __restrict__ pf,      // [B][C][NPTS]
              const int*   __restrict__ cid,     // [B][NPTS], -1..K-1
              float*       __restrict__ out_pf)  // [B][NPTS][C]
{
    // Transposed tile, row pad 33 words:
    //  - fill STS  bank = (tid + c)        mod 32  -> conflict-free
    //  - segmax LDS bank = (row + lane)    mod 32  -> conflict-free
    //  - out LDS   bank = (j + 4(l%8) + m) mod 32  -> bijection, conflict-free
    __shared__ float featT[CHUNK][CTILE + 1];
    __shared__ int   cid_sh[CHUNK];

    const int s    = blockIdx.x;           // n-split
    const int c0   = blockIdx.y * CTILE;   // channel tile base
    const int b    = blockIdx.z;           // batch
    const int tid  = threadIdx.x;
    const int lane = tid & 31;
    const int w    = tid >> 5;             // warp id: owns clusters [16w, 16w+16)
    const int n_base = s * NPB;

    // 16 register accumulators per lane: (cluster = 16w+kk, channel = c0+lane)
    float acc[16];
#pragma unroll
    for (int kk = 0; kk < 16; kk++) acc[kk] = NEG_SENT;

    const float* pf_base = pf + (size_t)(b * C + c0) * NPTS + n_base;

    for (int chunk = 0; chunk < NPB; chunk += CHUNK) {
        const int n0 = n_base + chunk;

        cid_sh[tid] = cid[b * NPTS + n0 + tid];

        // Fill: lane index == n (coalesced 128B LDG per warp), scalar STS,
        // fully unrolled -> 32 outstanding loads (high MLP).
#pragma unroll
        for (int c = 0; c < CTILE; c++) {
            featT[tid][c] = pf_base[(size_t)c * NPTS + chunk + tid];
        }
        __syncthreads();

        // Transpose output: thread = (point-group p, channel-quad q).
        // 4 conflict-free scalar LDS -> one STG.128; 8 lanes cover one point's
        // 32 channels = 128B contiguous.
        {
            const int p = tid >> 3;        // 0..31
            const int q = tid & 7;         // 0..7
#pragma unroll
            for (int r = 0; r < CHUNK / 32; r++) {   // 8 iters
                const int j = r * 32 + p;
                float4 v;
                v.x = featT[j][4 * q + 0];
                v.y = featT[j][4 * q + 1];
                v.z = featT[j][4 * q + 2];
                v.w = featT[j][4 * q + 3];
                *reinterpret_cast<float4*>(
                    &out_pf[(size_t)(b * NPTS + n0 + j) * C + c0 + 4 * q]) = v;
            }
        }

        // Segment max, atomic-free: warp w scans all points, selects its 16
        // clusters via ballot; matched rows are broadcast-uniform j with lanes
        // sweeping channels (conflict-free LDS).
#pragma unroll 1
        for (int base = 0; base < CHUNK; base += 32) {
            int rel = cid_sh[base + lane] - w * 16;   // in [0,16) iff owned
#pragma unroll
            for (int kk = 0; kk < 16; kk++) {
                unsigned m = __ballot_sync(0xffffffffu, rel == kk);
                while (m) {
                    int j = __ffs(m) - 1;
                    m &= m - 1;
                    acc[kk] = fmaxf(acc[kk], featT[base + j][lane]);
                }
            }
        }
        __syncthreads();   // protect featT/cid_sh before next chunk overwrites
    }

    // Coalesced stores of this split's partial maxima (sentinel kept for empty).
#pragma unroll
    for (int kk = 0; kk < 16; kk++) {
        int k = w * 16 + kk;
        g_scratch[((size_t)(s * B + b) * K + k) * C + c0 + lane] = acc[kk];
    }
}

__global__ __launch_bounds__(256)
void seg_finalize(float* __restrict__ out_seg)   // [B*K][C]
{
    int t = blockIdx.x * blockDim.x + threadIdx.x;
    if (t >= BKC) return;
    float m = NEG_SENT;
#pragma unroll
    for (int s = 0; s < NSPLIT; s++)
        m = fmaxf(m, g_scratch[(size_t)s * BKC + t]);
    // empty segment -> 0.0 (matches reference's isfinite -> 0 replacement)
    out_seg[t] = (m > EMPTY_TH) ? m : 0.0f;
}

extern "C" void kernel_launch(void* const* d_in, const int* in_sizes, int n_in,
                              void* d_out, int out_size)
{
    // Identify inputs by element count (robust to metadata ordering):
    // point_features = B*C*NPTS = 33,554,432 ; cluster_ids = B*NPTS = 131,072
    const float* pf  = (const float*)d_in[0];
    const int*   cid = (const int*)d_in[1];
    if (in_sizes[0] == B * NPTS) {
        pf  = (const float*)d_in[1];
        cid = (const int*)d_in[0];
    }

    float* out     = (float*)d_out;
    float* out_seg = out;            // [B*K, C]   (first tuple element)
    float* out_pf  = out + BKC;      // [B*N, C]   (second tuple element)

    dim3 grid(NSPLIT, C / CTILE, B); // 8 x 8 x 8 = 512 blocks, single wave
    seg_main<<<grid, 256>>>(pf, cid, out_pf);
    seg_finalize<<<(BKC + 255) / 256, 256>>>(out_seg);
}

// round 3
// speedup vs baseline: 1.0563x; 1.0563x over previous
#include <cuda_runtime.h>
#include <math.h>

#define B      8
#define C      256
#define NPTS   16384
#define K      128
#define CTILE  32
#define CHUNK  256
#define NSPLIT 8
#define NPB    (NPTS / NSPLIT)   // 2048 points per block
#define BKC    (B * K * C)       // 262144

#define NEG_SENT (-3.402823e38f) // -FLT_MAX sentinel (fast-math safe, no inf)
#define EMPTY_TH (-3.3e38f)

// Per-split partial maxima: [NSPLIT][B][K][C] = 8 MiB. Every slot written
// unconditionally each launch -> no init kernel, graph-replay deterministic.
__device__ float g_scratch[NSPLIT * B * K * C];

__global__ __launch_bounds__(256)
void seg_main(const float* __restrict__ pf,      // [B][C][NPTS]
              const int*   __restrict__ cid,     // [B][NPTS], -1..K-1
              float*       __restrict__ out_pf)  // [B][NPTS][C]
{
    // Transposed tile, pad 33 words. Bank math (all conflict-free):
    //  fill STS   : bank = (4*(l&7)+u + 4w+(l>>3)) mod 32  -> bijective
    //  segmax LDS : row uniform, lanes sweep +1              -> bijective
    //  out LDS    : bank = ((l>>3) + 4*(l&7) + m) mod 32     -> bijective
    __shared__ float featT[CHUNK][CTILE + 1];
    __shared__ int   cid_sh[CHUNK];
    // Per-warp private segment-max accumulators (lanes sweep 32 consecutive
    // words -> conflict-free; only warp w ever touches acc_sh[w]).
    __shared__ float acc_sh[8][16][CTILE];

    const int s    = blockIdx.x;           // n-split
    const int c0   = blockIdx.y * CTILE;   // channel tile base
    const int b    = blockIdx.z;           // batch
    const int tid  = threadIdx.x;
    const int lane = tid & 31;
    const int w    = tid >> 5;             // warp owns clusters [16w, 16w+16)
    const int n_base = s * NPB;

    // Init accumulators (ordered before first use by chunk-0's __syncthreads)
    {
        float* af = &acc_sh[0][0][0];
#pragma unroll
        for (int i = 0; i < (8 * 16 * CTILE) / 256; i++)
            af[tid + i * 256] = NEG_SENT;
    }

    const float* pf_base = pf + (size_t)(b * C + c0) * NPTS + n_base;
    const int cfill = w * 4 + (lane >> 3);   // channel handled in fill (0..31)
    const int jq    = lane & 7;              // n-quad handled in fill
    const int p     = tid >> 3;              // point-group for transpose-out
    const int q     = tid & 7;               // channel-quad for transpose-out

#pragma unroll 1
    for (int chunk = 0; chunk < NPB; chunk += CHUNK) {
        const int n0 = n_base + chunk;

        cid_sh[tid] = cid[b * NPTS + n0 + tid];

        // Fill: LDG.128 over n (128B coalesced per channel-row), STS transposed.
#pragma unroll
        for (int it = 0; it < CHUNK / 32; it++) {      // 8
            const float4 v = *reinterpret_cast<const float4*>(
                &pf_base[(size_t)cfill * NPTS + chunk + 4 * (jq + 8 * it)]);
            const int row = 4 * jq + 32 * it;
            featT[row + 0][cfill] = v.x;
            featT[row + 1][cfill] = v.y;
            featT[row + 2][cfill] = v.z;
            featT[row + 3][cfill] = v.w;
        }
        __syncthreads();

        // Transpose-out: 4 conflict-free scalar LDS -> one 16B STG;
        // 8 lanes cover one point's 32 channels = 128B coalesced.
#pragma unroll
        for (int r = 0; r < CHUNK / 32; r++) {         // 8
            const int j = r * 32 + p;
            float4 v;
            v.x = featT[j][4 * q + 0];
            v.y = featT[j][4 * q + 1];
            v.z = featT[j][4 * q + 2];
            v.w = featT[j][4 * q + 3];
            *reinterpret_cast<float4*>(
                &out_pf[(size_t)(b * NPTS + n0 + j) * C + c0 + 4 * q]) = v;
        }

        // Segment-max: ONE ballot per 32-point batch; iterate matched bits
        // (avg ~4) updating per-warp smem accumulators (dynamic kk is fine
        // in smem). All lanes follow identical uniform (j, kk).
#pragma unroll 1
        for (int base = 0; base < CHUNK; base += 32) {
            const int  myc = cid_sh[base + lane];
            unsigned m = __ballot_sync(0xffffffffu,
                                       (unsigned)(myc - w * 16) < 16u);
            while (m) {
                const int j = __ffs(m) - 1;
                m &= m - 1;
                const int kk = cid_sh[base + j] - w * 16;   // uniform bcast LDS
                const float v = featT[base + j][lane];
                float* a = &acc_sh[w][kk][lane];
                *a = fmaxf(*a, v);
            }
        }
        __syncthreads();   // protect featT/cid_sh before next chunk
    }

    // Coalesced partial-max stores (sentinel kept for empty segments).
#pragma unroll
    for (int kk = 0; kk < 16; kk++) {
        const int k = w * 16 + kk;
        g_scratch[((size_t)(s * B + b) * K + k) * C + c0 + lane]
            = acc_sh[w][kk][lane];
    }
}

__global__ __launch_bounds__(256)
void seg_finalize(float* __restrict__ out_seg)   // [B*K][C]
{
    const int t = blockIdx.x * blockDim.x + threadIdx.x;   // over BKC/4
    if (t >= BKC / 4) return;
    const float4* sc = reinterpret_cast<const float4*>(g_scratch);
    float4 m = sc[t];
#pragma unroll
    for (int s = 1; s < NSPLIT; s++) {
        float4 v = sc[(size_t)s * (BKC / 4) + t];
        m.x = fmaxf(m.x, v.x); m.y = fmaxf(m.y, v.y);
        m.z = fmaxf(m.z, v.z); m.w = fmaxf(m.w, v.w);
    }
    float4 o;
    o.x = (m.x > EMPTY_TH) ? m.x : 0.0f;
    o.y = (m.y > EMPTY_TH) ? m.y : 0.0f;
    o.z = (m.z > EMPTY_TH) ? m.z : 0.0f;
    o.w = (m.w > EMPTY_TH) ? m.w : 0.0f;
    reinterpret_cast<float4*>(out_seg)[t] = o;
}

extern "C" void kernel_launch(void* const* d_in, const int* in_sizes, int n_in,
                              void* d_out, int out_size)
{
    const float* pf  = (const float*)d_in[0];
    const int*   cid = (const int*)d_in[1];
    if (in_sizes[0] == B * NPTS) {   // robust to metadata ordering
        pf  = (const float*)d_in[1];
        cid = (const int*)d_in[0];
    }

    float* out     = (float*)d_out;
    float* out_seg = out;            // [B*K, C]
    float* out_pf  = out + BKC;      // [B*N, C]

    dim3 grid(NSPLIT, C / CTILE, B); // 512 blocks, single wave
    seg_main<<<grid, 256>>>(pf, cid, out_pf);
    seg_finalize<<<(BKC / 4 + 255) / 256, 256>>>(out_seg);
}